// round 16
// baseline (speedup 1.0000x reference)
#include <cuda_runtime.h>
#include <cuda_fp16.h>
#include <math.h>

#define T_STEPS 1024
#define NMC     32768
#define NCTA    148
#define NWARPS  14
#define TPB     (NWARPS * 32)   // 448 (table kernel)
#define MTPB    224              // scan kernel threads

#define NG      1024             // z-grid points
#define ZMIN    (-32.0f)
#define ZSPAN   64.0f
#define GH      (ZSPAN / (float)(NG - 1))
#define INVH    ((float)(NG - 1) / ZSPAN)
#define NZT     (NG / 16)        // 64 z-tiles
#define NTASKS  (T_STEPS * NZT)  // 65536
#define TWARPS  (NCTA * NWARPS)  // 2072 table warps
#define ROWCH   (NG * 8 / 16)    // 16B chunks per row = 512

// ---- scratch (__device__ globals) -------------------------------------------
__device__ uint2   g_c1p[2 * T_STEPS * 16];
__device__ __half2 g_w05h[2 * 32];
__device__ float   g_mu[T_STEPS];
__device__ float   g_part[NCTA];
__device__ float2  g_tab[T_STEPS * NG];   // (F, G) per (t, z-grid point): 8MB

// ---------------------------------------------------------------------------
// Prep: per-step layer-1 constants (0.5-scaled, fragment-packed) + mu(t)
// ---------------------------------------------------------------------------
__global__ void prep_kernel(const float* __restrict__ X_seq,
                            const float* __restrict__ a,
                            const float* __restrict__ b0p,
                            const float* __restrict__ b1p,
                            const float* __restrict__ b2p,
                            const float* __restrict__ Sp,
                            const float* __restrict__ dW1,
                            const float* __restrict__ db1,
                            const float* __restrict__ gW1,
                            const float* __restrict__ gb1,
                            const int*   __restrict__ i0p)
{
    int t = blockIdx.x;
    int j = threadIdx.x;
    int i0 = *i0p;
    float tk = (float)(i0 + t);
    const float* x = X_seq + (size_t)(i0 + t) * 3;
    float x0 = x[0], x1 = x[1], x2 = x[2];

    int net = j >> 6, s = j & 63;
    const float* W1 = net ? gW1 : dW1;
    const float* B1 = net ? gb1 : db1;

    if (s < 16) {
        int kt = s >> 2, tg = s & 3;
        int pl = kt * 8 + tg, ph = pl + 4;
        float v[4];
        int cols[4] = {2 * pl, 2 * pl + 1, 2 * ph, 2 * ph + 1};
#pragma unroll
        for (int q = 0; q < 4; q++) {
            int c = cols[q];
            v[q] = B1[c] + x0 * W1[64 + c] + x1 * W1[128 + c]
                         + x2 * W1[192 + c] + tk * W1[256 + c];
        }
        __half2 lo = __floats2half2_rn(0.5f * v[0], 0.5f * v[1]);
        __half2 hi = __floats2half2_rn(0.5f * v[2], 0.5f * v[3]);
        uint2 out;
        out.x = *reinterpret_cast<unsigned*>(&lo);
        out.y = *reinterpret_cast<unsigned*>(&hi);
        g_c1p[(net * T_STEPS + t) * 16 + s] = out;
    }
    if (s >= 32 && s < 64 && t == 0) {
        int p = s - 32;
        g_w05h[net * 32 + p] = __floats2half2_rn(0.5f * W1[2 * p],
                                                 0.5f * W1[2 * p + 1]);
    }
    if (j == 0) {
        float w = 6.283185307179586f * tk / (*Sp);
        g_mu[t] = x0 * a[0] + x1 * a[1] + x2 * a[2]
                + (*b0p) + (*b1p) * sinf(w) + (*b2p) * cosf(w);
    }
}

__global__ void nop_kernel() {}

// ---------------------------------------------------------------------------
// helpers (identical numerics to R7 best)
// ---------------------------------------------------------------------------
__device__ __forceinline__ unsigned silu2h(__half2 m) {
    unsigned mi = *reinterpret_cast<unsigned*>(&m), ti;
    asm("tanh.approx.f16x2 %0, %1;\n" : "=r"(ti) : "r"(mi));
    __half2 tt = *reinterpret_cast<__half2*>(&ti);
    __half2 h = __hfma2(m, tt, m);
    return *reinterpret_cast<unsigned*>(&h);
}
__device__ __forceinline__ void mma16816_f(float& c0, float& c1, float& c2, float& c3,
                                           unsigned a0, unsigned a1, unsigned a2, unsigned a3,
                                           unsigned b0, unsigned b1)
{
    asm volatile("mma.sync.aligned.m16n8k16.row.col.f32.f16.f16.f32 "
                 "{%0,%1,%2,%3}, {%4,%5,%6,%7}, {%8,%9}, {%0,%1,%2,%3};\n"
                 : "+f"(c0), "+f"(c1), "+f"(c2), "+f"(c3)
                 : "r"(a0), "r"(a1), "r"(a2), "r"(a3), "r"(b0), "r"(b1));
}
__device__ __forceinline__ void mma16816_h(unsigned& d0, unsigned& d1,
                                           unsigned a0, unsigned a1, unsigned a2, unsigned a3,
                                           unsigned b0, unsigned b1)
{
    asm volatile("mma.sync.aligned.m16n8k16.row.col.f16.f16.f16.f16 "
                 "{%0,%1}, {%2,%3,%4,%5}, {%6,%7}, {%0,%1};\n"
                 : "+r"(d0), "+r"(d1)
                 : "r"(a0), "r"(a1), "r"(a2), "r"(a3), "r"(b0), "r"(b1));
}

// ---------------------------------------------------------------------------
// Table kernel: F(z,t), G(z,t) on the z-grid (R7 step-body clone).
// ---------------------------------------------------------------------------
__global__ void __launch_bounds__(TPB, 1) table_kernel(
    const float* __restrict__ kappap,
    const float* __restrict__ dW2, const float* __restrict__ db2,
    const float* __restrict__ dW3, const float* __restrict__ db3,
    const float* __restrict__ gW2, const float* __restrict__ gb2,
    const float* __restrict__ gW3, const float* __restrict__ gb3)
{
    __shared__ uint4 Bp[2][16 * 32];

    int tid  = threadIdx.x;
    int lane = tid & 31, warp = tid >> 5;
    int g = lane >> 2, tg = lane & 3;

    {
        const float* W2n[2] = { dW2, gW2 };
        for (int e = tid; e < 2 * 16 * 32; e += TPB) {
            int nn  = e >> 9;
            int rem = e & 511;
            int idx = rem >> 5;
            int ll  = rem & 31;
            int gg = ll >> 2, tq = ll & 3;
            int ktp = idx >> 2, kt = idx & 3;
            int n0 = ktp * 16 + gg, n1 = ktp * 16 + 8 + gg;
            int k0 = kt * 16 + 2 * tq;
            const float* W2 = W2n[nn];
            __half2 x0 = __floats2half2_rn(W2[k0 * 64 + n0],       W2[(k0 + 1) * 64 + n0]);
            __half2 y0 = __floats2half2_rn(W2[(k0 + 8) * 64 + n0], W2[(k0 + 9) * 64 + n0]);
            __half2 x1 = __floats2half2_rn(W2[k0 * 64 + n1],       W2[(k0 + 1) * 64 + n1]);
            __half2 y1 = __floats2half2_rn(W2[(k0 + 8) * 64 + n1], W2[(k0 + 9) * 64 + n1]);
            uint4 v;
            v.x = *reinterpret_cast<unsigned*>(&x0);
            v.y = *reinterpret_cast<unsigned*>(&y0);
            v.z = *reinterpret_cast<unsigned*>(&x1);
            v.w = *reinterpret_cast<unsigned*>(&y1);
            Bp[nn][idx * 32 + ll] = v;
        }
    }
    __syncthreads();

    float kappa = *kappap;

    __half2 wh[2][4][2];
#pragma unroll
    for (int net = 0; net < 2; net++)
#pragma unroll
        for (int kt = 0; kt < 4; kt++) {
            wh[net][kt][0] = __ldg(g_w05h + net * 32 + kt * 8 + tg);
            wh[net][kt][1] = __ldg(g_w05h + net * 32 + kt * 8 + tg + 4);
        }
    __half2 hb2[2][8];
#pragma unroll
    for (int nt = 0; nt < 8; nt++) {
        int c = nt * 8 + 2 * tg;
        hb2[0][nt] = __floats2half2_rn(0.5f * db2[c], 0.5f * db2[c + 1]);
        hb2[1][nt] = __floats2half2_rn(0.5f * gb2[c], 0.5f * gb2[c + 1]);
    }
    unsigned bw3[2][4][2];
#pragma unroll
    for (int net = 0; net < 2; net++) {
        const float* W3 = net ? gW3 : dW3;
#pragma unroll
        for (int kp = 0; kp < 4; kp++) {
            if (g == 0) {
                int k0 = kp * 16 + 2 * tg;
                __half2 l = __floats2half2_rn(W3[k0],     W3[k0 + 1]);
                __half2 h = __floats2half2_rn(W3[k0 + 8], W3[k0 + 9]);
                bw3[net][kp][0] = *reinterpret_cast<unsigned*>(&l);
                bw3[net][kp][1] = *reinterpret_cast<unsigned*>(&h);
            } else { bw3[net][kp][0] = 0u; bw3[net][kp][1] = 0u; }
        }
    }
    float b3[2] = { db3[0], gb3[0] };

    const __half2 h05 = __floats2half2_rn(0.5f, 0.5f);
    int src = 4 * (lane & 7);

    for (int task = blockIdx.x * NWARPS + warp; task < NTASKS; task += TWARPS) {
        int t     = task >> 6;           // / NZT
        int ztile = task & (NZT - 1);
        int zbase = ztile * 16;

        float zg  = ZMIN + GH * (float)(zbase + g);
        float zg8 = ZMIN + GH * (float)(zbase + g + 8);
        __half2 zh0 = __half2half2(__float2half(zg));
        __half2 zh1 = __half2half2(__float2half(zg8));

        float mu = g_mu[t];
        uint2 cc[2][4];
#pragma unroll
        for (int net = 0; net < 2; net++) {
            const uint2* c1t = g_c1p + (size_t)(net * T_STEPS + t) * 16;
#pragma unroll
            for (int kt = 0; kt < 4; kt++)
                cc[net][kt] = __ldg(c1t + kt * 4 + tg);
        }

        float fg[2];
#pragma unroll
        for (int net = 0; net < 2; net++) {
            unsigned A[4][4];
#pragma unroll
            for (int kt = 0; kt < 4; kt++) {
                __half2 clo = *reinterpret_cast<__half2*>(&cc[net][kt].x);
                __half2 chi = *reinterpret_cast<__half2*>(&cc[net][kt].y);
                __half2 wlo = wh[net][kt][0], whi = wh[net][kt][1];
                A[kt][0] = silu2h(__hfma2(zh0, wlo, clo));
                A[kt][1] = silu2h(__hfma2(zh1, wlo, clo));
                A[kt][2] = silu2h(__hfma2(zh0, whi, chi));
                A[kt][3] = silu2h(__hfma2(zh1, whi, chi));
            }

            float da0 = (tg == 0) ? b3[net] : 0.0f, da1 = 0.0f;
            float da2 = (tg == 0) ? b3[net] : 0.0f, da3 = 0.0f;
            float db0 = 0.0f, db1_ = 0.0f, db2_ = 0.0f, db3_ = 0.0f;

#pragma unroll
            for (int ktp = 0; ktp < 4; ktp++) {
                unsigned acc[2][2];
                acc[0][0] = acc[0][1] = acc[1][0] = acc[1][1] = 0u;
#pragma unroll
                for (int kt = 0; kt < 4; kt++) {
                    uint4 b = Bp[net][(ktp * 4 + kt) * 32 + lane];
                    mma16816_h(acc[0][0], acc[0][1],
                               A[kt][0], A[kt][1], A[kt][2], A[kt][3], b.x, b.y);
                    mma16816_h(acc[1][0], acc[1][1],
                               A[kt][0], A[kt][1], A[kt][2], A[kt][3], b.z, b.w);
                }
                __half2 bb0 = hb2[net][2 * ktp], bb1 = hb2[net][2 * ktp + 1];
                __half2 a00 = *reinterpret_cast<__half2*>(&acc[0][0]);
                __half2 a01 = *reinterpret_cast<__half2*>(&acc[0][1]);
                __half2 a10 = *reinterpret_cast<__half2*>(&acc[1][0]);
                __half2 a11 = *reinterpret_cast<__half2*>(&acc[1][1]);
                unsigned e0 = silu2h(__hfma2(a00, h05, bb0));
                unsigned e1 = silu2h(__hfma2(a01, h05, bb0));
                unsigned e2 = silu2h(__hfma2(a10, h05, bb1));
                unsigned e3 = silu2h(__hfma2(a11, h05, bb1));
                if (ktp & 1)
                    mma16816_f(db0, db1_, db2_, db3_, e0, e1, e2, e3,
                               bw3[net][ktp][0], bw3[net][ktp][1]);
                else
                    mma16816_f(da0, da1, da2, da3, e0, e1, e2, e3,
                               bw3[net][ktp][0], bw3[net][ktp][1]);
            }

            float d0 = da0 + db0;
            float d2 = da2 + db2_;
            float v0 = __shfl_sync(0xffffffffu, d0, src);
            float v2 = __shfl_sync(0xffffffffu, d2, src);
            fg[net] = (lane & 8) ? v2 : v0;
        }

        if (lane < 16) {
            float zl = ZMIN + GH * (float)(zbase + lane);
            float F = kappa * (mu - zl) + fg[0];
            float graw = fg[1];
            float G = fmaxf(graw, 0.0f)
                    + __logf(1.0f + __expf(-fabsf(graw))) + 1e-6f;
            g_tab[(size_t)t * NG + zbase + lane] = make_float2(F, G);
        }
    }
}

// ---------------------------------------------------------------------------
// Scan: 1 thread/path; double-buffered cp.async row staging in SMEM.
// ---------------------------------------------------------------------------
__global__ void __launch_bounds__(MTPB, 1) scan_kernel(
    const float* __restrict__ y_seq,
    const float* __restrict__ xi,
    const int*   __restrict__ i0p)
{
    __shared__ float2 sbuf[2][NG];            // 16 KB
    __shared__ float red[MTPB / 32];

    int tid  = threadIdx.x;
    int lane = tid & 31, warp = tid >> 5;
    int path = blockIdx.x * MTPB + tid;
    bool active = (path < NMC);
    int pc = active ? path : (NMC - 1);       // clamped path for loads
    int i0 = *i0p;

    // prologue: prefetch row 0 into sbuf[0]
    {
        const char* src = (const char*)g_tab;
        unsigned sbase = (unsigned)__cvta_generic_to_shared(&sbuf[0][0]);
        for (int c = tid; c < ROWCH; c += MTPB) {
            asm volatile("cp.async.cg.shared.global [%0], [%1], 16;\n"
                         :: "r"(sbase + c * 16), "l"(src + c * 16));
        }
        asm volatile("cp.async.commit_group;\n");
    }

    float y0 = fminf(fmaxf(y_seq[i0 - 1], 1e-4f), 1.0f - 1e-4f);
    float z  = logf(y0 / (1.0f - y0));
    const float* yobs = y_seq + i0;
    float ssum = 0.0f;
    float xik_next = __ldg(xi + pc);

    for (int t = 0; t < T_STEPS; t++) {
        asm volatile("cp.async.wait_group 0;\n" ::: "memory");
        __syncthreads();                       // row t ready in sbuf[t&1]

        // prefetch row t+1 into the other buffer
        if (t + 1 < T_STEPS) {
            const char* src = (const char*)(g_tab + (size_t)(t + 1) * NG);
            unsigned sbase = (unsigned)__cvta_generic_to_shared(&sbuf[(t + 1) & 1][0]);
            for (int c = tid; c < ROWCH; c += MTPB) {
                asm volatile("cp.async.cg.shared.global [%0], [%1], 16;\n"
                             :: "r"(sbase + c * 16), "l"(src + c * 16));
            }
        }
        asm volatile("cp.async.commit_group;\n" ::: "memory");

        float xik = xik_next;
        int tn = (t + 1 < T_STEPS) ? (t + 1) : t;
        xik_next = __ldg(xi + (size_t)tn * NMC + pc);
        float yt = __ldg(yobs + t) - 0.5f;

        // grid position (stencil i-1..i+2 clamped in range)
        float u = fmaf(z, INVH, -ZMIN * INVH);
        u = fminf(fmaxf(u, 1.0f), (float)(NG - 3));
        int i = (int)u;
        if (i > NG - 3) i = NG - 3;
        float s = u - (float)i;

        const float2* row = sbuf[t & 1];
        float2 pm = row[i - 1];
        float2 p0 = row[i];
        float2 p1 = row[i + 1];
        float2 p2 = row[i + 2];

        float sm1 = s - 1.0f, sm2 = s - 2.0f, sp1 = s + 1.0f;
        float wm = -s * sm1 * sm2 * (1.0f / 6.0f);
        float w0 =  sp1 * sm1 * sm2 * 0.5f;
        float w1 = -sp1 * s * sm2 * 0.5f;
        float w2 =  sp1 * s * sm1 * (1.0f / 6.0f);

        float F = wm * pm.x + w0 * p0.x + w1 * p1.x + w2 * p2.x;
        float G = wm * pm.y + w0 * p0.y + w1 * p1.y + w2 * p2.y;

        z = z + F + G * xik;

        float th;
        asm("tanh.approx.f32 %0, %1;\n" : "=f"(th) : "f"(0.5f * z));
        float dy = yt - 0.5f * th;
        ssum = fmaf(dy, dy, ssum);

        __syncthreads();                       // all reads of sbuf[t&1] done
    }

    if (!active) ssum = 0.0f;

#pragma unroll
    for (int o = 16; o; o >>= 1) ssum += __shfl_xor_sync(0xffffffffu, ssum, o);
    if (lane == 0) red[warp] = ssum;
    __syncthreads();
    if (warp == 0) {
        float s = (lane < MTPB / 32) ? red[lane] : 0.0f;
#pragma unroll
        for (int o = 4; o; o >>= 1) s += __shfl_xor_sync(0xffffffffu, s, o);
        if (lane == 0) g_part[blockIdx.x] = s;
    }
}

// ---------------------------------------------------------------------------
__global__ void fin_kernel(const float* __restrict__ lsop, float* __restrict__ out)
{
    int lane = threadIdx.x;
    float s = 0.0f;
    for (int i = lane; i < NCTA; i += 32) s += g_part[i];
#pragma unroll
    for (int o = 16; o; o >>= 1) s += __shfl_xor_sync(0xffffffffu, s, o);
    if (lane == 0) {
        float lso = *lsop;
        float sig = expf(lso) + 1e-8f;
        out[0] = 0.5f * s / ((float)T_STEPS * (float)NMC) / (sig * sig) + lso;
    }
}

// ---------------------------------------------------------------------------
extern "C" void kernel_launch(void* const* d_in, const int* in_sizes, int n_in,
                              void* d_out, int out_size)
{
    const float* X_seq = (const float*)d_in[0];
    const float* y_seq = (const float*)d_in[1];
    const float* kappa = (const float*)d_in[2];
    const float* a     = (const float*)d_in[3];
    const float* b0    = (const float*)d_in[4];
    const float* b1    = (const float*)d_in[5];
    const float* b2    = (const float*)d_in[6];
    const float* S     = (const float*)d_in[7];
    const float* lso   = (const float*)d_in[8];
    const float* dW1   = (const float*)d_in[9];
    const float* db1   = (const float*)d_in[10];
    const float* dW2   = (const float*)d_in[11];
    const float* db2   = (const float*)d_in[12];
    const float* dW3   = (const float*)d_in[13];
    const float* db3   = (const float*)d_in[14];
    const float* gW1   = (const float*)d_in[15];
    const float* gb1   = (const float*)d_in[16];
    const float* gW2   = (const float*)d_in[17];
    const float* gb2   = (const float*)d_in[18];
    const float* gW3   = (const float*)d_in[19];
    const float* gb3   = (const float*)d_in[20];
    const float* xi    = (const float*)d_in[21];
    const int*   i0    = (const int*)d_in[22];

    prep_kernel<<<T_STEPS, 128>>>(X_seq, a, b0, b1, b2, S, dW1, db1, gW1, gb1, i0);
    table_kernel<<<NCTA, TPB>>>(kappa, dW2, db2, dW3, db3, gW2, gb2, gW3, gb3);
    nop_kernel<<<1, 32>>>();   // padding: ncu -s 5 -> scan_kernel
    scan_kernel<<<NCTA, MTPB>>>(y_seq, xi, i0);
    fin_kernel<<<1, 32>>>(lso, (float*)d_out);
}

// round 17
// speedup vs baseline: 1.5431x; 1.5431x over previous
#include <cuda_runtime.h>
#include <cuda_fp16.h>
#include <math.h>

#define T_STEPS 1024
#define NMC     32768
#define NCTA    148
#define NWARPS  14
#define TPB     (NWARPS * 32)   // 448 (table kernel)
#define MTPB    224              // scan kernel threads

#define NG      1024             // z-grid points
#define ZMIN    (-32.0f)
#define ZSPAN   64.0f
#define GH      (ZSPAN / (float)(NG - 1))
#define INVH    ((float)(NG - 1) / ZSPAN)
#define NZT     (NG / 16)        // 64 z-tiles
#define NTASKS  (T_STEPS * NZT)  // 65536
#define TWARPS  (NCTA * NWARPS)  // 2072 table warps
#define ROWLN   (NG * 8 / 128)   // 128B lines per row = 64

// ---- scratch (__device__ globals) -------------------------------------------
__device__ uint2   g_c1p[2 * T_STEPS * 16];
__device__ __half2 g_w05h[2 * 32];
__device__ float   g_mu[T_STEPS];
__device__ float   g_part[NCTA];
__device__ float2  g_tab[T_STEPS * NG];   // (F, G) per (t, z-grid point): 8MB

// ---------------------------------------------------------------------------
// Prep: per-step layer-1 constants (0.5-scaled, fragment-packed) + mu(t)
// ---------------------------------------------------------------------------
__global__ void prep_kernel(const float* __restrict__ X_seq,
                            const float* __restrict__ a,
                            const float* __restrict__ b0p,
                            const float* __restrict__ b1p,
                            const float* __restrict__ b2p,
                            const float* __restrict__ Sp,
                            const float* __restrict__ dW1,
                            const float* __restrict__ db1,
                            const float* __restrict__ gW1,
                            const float* __restrict__ gb1,
                            const int*   __restrict__ i0p)
{
    int t = blockIdx.x;
    int j = threadIdx.x;
    int i0 = *i0p;
    float tk = (float)(i0 + t);
    const float* x = X_seq + (size_t)(i0 + t) * 3;
    float x0 = x[0], x1 = x[1], x2 = x[2];

    int net = j >> 6, s = j & 63;
    const float* W1 = net ? gW1 : dW1;
    const float* B1 = net ? gb1 : db1;

    if (s < 16) {
        int kt = s >> 2, tg = s & 3;
        int pl = kt * 8 + tg, ph = pl + 4;
        float v[4];
        int cols[4] = {2 * pl, 2 * pl + 1, 2 * ph, 2 * ph + 1};
#pragma unroll
        for (int q = 0; q < 4; q++) {
            int c = cols[q];
            v[q] = B1[c] + x0 * W1[64 + c] + x1 * W1[128 + c]
                         + x2 * W1[192 + c] + tk * W1[256 + c];
        }
        __half2 lo = __floats2half2_rn(0.5f * v[0], 0.5f * v[1]);
        __half2 hi = __floats2half2_rn(0.5f * v[2], 0.5f * v[3]);
        uint2 out;
        out.x = *reinterpret_cast<unsigned*>(&lo);
        out.y = *reinterpret_cast<unsigned*>(&hi);
        g_c1p[(net * T_STEPS + t) * 16 + s] = out;
    }
    if (s >= 32 && s < 64 && t == 0) {
        int p = s - 32;
        g_w05h[net * 32 + p] = __floats2half2_rn(0.5f * W1[2 * p],
                                                 0.5f * W1[2 * p + 1]);
    }
    if (j == 0) {
        float w = 6.283185307179586f * tk / (*Sp);
        g_mu[t] = x0 * a[0] + x1 * a[1] + x2 * a[2]
                + (*b0p) + (*b1p) * sinf(w) + (*b2p) * cosf(w);
    }
}

__global__ void nop_kernel() {}

// ---------------------------------------------------------------------------
// helpers (identical numerics to R7 best)
// ---------------------------------------------------------------------------
__device__ __forceinline__ unsigned silu2h(__half2 m) {
    unsigned mi = *reinterpret_cast<unsigned*>(&m), ti;
    asm("tanh.approx.f16x2 %0, %1;\n" : "=r"(ti) : "r"(mi));
    __half2 tt = *reinterpret_cast<__half2*>(&ti);
    __half2 h = __hfma2(m, tt, m);
    return *reinterpret_cast<unsigned*>(&h);
}
__device__ __forceinline__ void mma16816_f(float& c0, float& c1, float& c2, float& c3,
                                           unsigned a0, unsigned a1, unsigned a2, unsigned a3,
                                           unsigned b0, unsigned b1)
{
    asm volatile("mma.sync.aligned.m16n8k16.row.col.f32.f16.f16.f32 "
                 "{%0,%1,%2,%3}, {%4,%5,%6,%7}, {%8,%9}, {%0,%1,%2,%3};\n"
                 : "+f"(c0), "+f"(c1), "+f"(c2), "+f"(c3)
                 : "r"(a0), "r"(a1), "r"(a2), "r"(a3), "r"(b0), "r"(b1));
}
__device__ __forceinline__ void mma16816_h(unsigned& d0, unsigned& d1,
                                           unsigned a0, unsigned a1, unsigned a2, unsigned a3,
                                           unsigned b0, unsigned b1)
{
    asm volatile("mma.sync.aligned.m16n8k16.row.col.f16.f16.f16.f16 "
                 "{%0,%1}, {%2,%3,%4,%5}, {%6,%7}, {%0,%1};\n"
                 : "+r"(d0), "+r"(d1)
                 : "r"(a0), "r"(a1), "r"(a2), "r"(a3), "r"(b0), "r"(b1));
}

// ---------------------------------------------------------------------------
// Table kernel: F(z,t), G(z,t) on the z-grid (R7 step-body clone).
// ---------------------------------------------------------------------------
__global__ void __launch_bounds__(TPB, 1) table_kernel(
    const float* __restrict__ kappap,
    const float* __restrict__ dW2, const float* __restrict__ db2,
    const float* __restrict__ dW3, const float* __restrict__ db3,
    const float* __restrict__ gW2, const float* __restrict__ gb2,
    const float* __restrict__ gW3, const float* __restrict__ gb3)
{
    __shared__ uint4 Bp[2][16 * 32];

    int tid  = threadIdx.x;
    int lane = tid & 31, warp = tid >> 5;
    int g = lane >> 2, tg = lane & 3;

    {
        const float* W2n[2] = { dW2, gW2 };
        for (int e = tid; e < 2 * 16 * 32; e += TPB) {
            int nn  = e >> 9;
            int rem = e & 511;
            int idx = rem >> 5;
            int ll  = rem & 31;
            int gg = ll >> 2, tq = ll & 3;
            int ktp = idx >> 2, kt = idx & 3;
            int n0 = ktp * 16 + gg, n1 = ktp * 16 + 8 + gg;
            int k0 = kt * 16 + 2 * tq;
            const float* W2 = W2n[nn];
            __half2 x0 = __floats2half2_rn(W2[k0 * 64 + n0],       W2[(k0 + 1) * 64 + n0]);
            __half2 y0 = __floats2half2_rn(W2[(k0 + 8) * 64 + n0], W2[(k0 + 9) * 64 + n0]);
            __half2 x1 = __floats2half2_rn(W2[k0 * 64 + n1],       W2[(k0 + 1) * 64 + n1]);
            __half2 y1 = __floats2half2_rn(W2[(k0 + 8) * 64 + n1], W2[(k0 + 9) * 64 + n1]);
            uint4 v;
            v.x = *reinterpret_cast<unsigned*>(&x0);
            v.y = *reinterpret_cast<unsigned*>(&y0);
            v.z = *reinterpret_cast<unsigned*>(&x1);
            v.w = *reinterpret_cast<unsigned*>(&y1);
            Bp[nn][idx * 32 + ll] = v;
        }
    }
    __syncthreads();

    float kappa = *kappap;

    __half2 wh[2][4][2];
#pragma unroll
    for (int net = 0; net < 2; net++)
#pragma unroll
        for (int kt = 0; kt < 4; kt++) {
            wh[net][kt][0] = __ldg(g_w05h + net * 32 + kt * 8 + tg);
            wh[net][kt][1] = __ldg(g_w05h + net * 32 + kt * 8 + tg + 4);
        }
    __half2 hb2[2][8];
#pragma unroll
    for (int nt = 0; nt < 8; nt++) {
        int c = nt * 8 + 2 * tg;
        hb2[0][nt] = __floats2half2_rn(0.5f * db2[c], 0.5f * db2[c + 1]);
        hb2[1][nt] = __floats2half2_rn(0.5f * gb2[c], 0.5f * gb2[c + 1]);
    }
    unsigned bw3[2][4][2];
#pragma unroll
    for (int net = 0; net < 2; net++) {
        const float* W3 = net ? gW3 : dW3;
#pragma unroll
        for (int kp = 0; kp < 4; kp++) {
            if (g == 0) {
                int k0 = kp * 16 + 2 * tg;
                __half2 l = __floats2half2_rn(W3[k0],     W3[k0 + 1]);
                __half2 h = __floats2half2_rn(W3[k0 + 8], W3[k0 + 9]);
                bw3[net][kp][0] = *reinterpret_cast<unsigned*>(&l);
                bw3[net][kp][1] = *reinterpret_cast<unsigned*>(&h);
            } else { bw3[net][kp][0] = 0u; bw3[net][kp][1] = 0u; }
        }
    }
    float b3[2] = { db3[0], gb3[0] };

    const __half2 h05 = __floats2half2_rn(0.5f, 0.5f);
    int src = 4 * (lane & 7);

    for (int task = blockIdx.x * NWARPS + warp; task < NTASKS; task += TWARPS) {
        int t     = task >> 6;           // / NZT
        int ztile = task & (NZT - 1);
        int zbase = ztile * 16;

        float zg  = ZMIN + GH * (float)(zbase + g);
        float zg8 = ZMIN + GH * (float)(zbase + g + 8);
        __half2 zh0 = __half2half2(__float2half(zg));
        __half2 zh1 = __half2half2(__float2half(zg8));

        float mu = g_mu[t];
        uint2 cc[2][4];
#pragma unroll
        for (int net = 0; net < 2; net++) {
            const uint2* c1t = g_c1p + (size_t)(net * T_STEPS + t) * 16;
#pragma unroll
            for (int kt = 0; kt < 4; kt++)
                cc[net][kt] = __ldg(c1t + kt * 4 + tg);
        }

        float fg[2];
#pragma unroll
        for (int net = 0; net < 2; net++) {
            unsigned A[4][4];
#pragma unroll
            for (int kt = 0; kt < 4; kt++) {
                __half2 clo = *reinterpret_cast<__half2*>(&cc[net][kt].x);
                __half2 chi = *reinterpret_cast<__half2*>(&cc[net][kt].y);
                __half2 wlo = wh[net][kt][0], whi = wh[net][kt][1];
                A[kt][0] = silu2h(__hfma2(zh0, wlo, clo));
                A[kt][1] = silu2h(__hfma2(zh1, wlo, clo));
                A[kt][2] = silu2h(__hfma2(zh0, whi, chi));
                A[kt][3] = silu2h(__hfma2(zh1, whi, chi));
            }

            float da0 = (tg == 0) ? b3[net] : 0.0f, da1 = 0.0f;
            float da2 = (tg == 0) ? b3[net] : 0.0f, da3 = 0.0f;
            float db0 = 0.0f, db1_ = 0.0f, db2_ = 0.0f, db3_ = 0.0f;

#pragma unroll
            for (int ktp = 0; ktp < 4; ktp++) {
                unsigned acc[2][2];
                acc[0][0] = acc[0][1] = acc[1][0] = acc[1][1] = 0u;
#pragma unroll
                for (int kt = 0; kt < 4; kt++) {
                    uint4 b = Bp[net][(ktp * 4 + kt) * 32 + lane];
                    mma16816_h(acc[0][0], acc[0][1],
                               A[kt][0], A[kt][1], A[kt][2], A[kt][3], b.x, b.y);
                    mma16816_h(acc[1][0], acc[1][1],
                               A[kt][0], A[kt][1], A[kt][2], A[kt][3], b.z, b.w);
                }
                __half2 bb0 = hb2[net][2 * ktp], bb1 = hb2[net][2 * ktp + 1];
                __half2 a00 = *reinterpret_cast<__half2*>(&acc[0][0]);
                __half2 a01 = *reinterpret_cast<__half2*>(&acc[0][1]);
                __half2 a10 = *reinterpret_cast<__half2*>(&acc[1][0]);
                __half2 a11 = *reinterpret_cast<__half2*>(&acc[1][1]);
                unsigned e0 = silu2h(__hfma2(a00, h05, bb0));
                unsigned e1 = silu2h(__hfma2(a01, h05, bb0));
                unsigned e2 = silu2h(__hfma2(a10, h05, bb1));
                unsigned e3 = silu2h(__hfma2(a11, h05, bb1));
                if (ktp & 1)
                    mma16816_f(db0, db1_, db2_, db3_, e0, e1, e2, e3,
                               bw3[net][ktp][0], bw3[net][ktp][1]);
                else
                    mma16816_f(da0, da1, da2, da3, e0, e1, e2, e3,
                               bw3[net][ktp][0], bw3[net][ktp][1]);
            }

            float d0 = da0 + db0;
            float d2 = da2 + db2_;
            float v0 = __shfl_sync(0xffffffffu, d0, src);
            float v2 = __shfl_sync(0xffffffffu, d2, src);
            fg[net] = (lane & 8) ? v2 : v0;
        }

        if (lane < 16) {
            float zl = ZMIN + GH * (float)(zbase + lane);
            float F = kappa * (mu - zl) + fg[0];
            float graw = fg[1];
            float G = fmaxf(graw, 0.0f)
                    + __logf(1.0f + __expf(-fabsf(graw))) + 1e-6f;
            g_tab[(size_t)t * NG + zbase + lane] = make_float2(F, G);
        }
    }
}

// ---------------------------------------------------------------------------
// Scan: 1 thread/path, barrier-free; L1 prefetch of row t+2 each step.
// ---------------------------------------------------------------------------
__global__ void __launch_bounds__(MTPB, 1) scan_kernel(
    const float* __restrict__ y_seq,
    const float* __restrict__ xi,
    const int*   __restrict__ i0p)
{
    __shared__ float red[MTPB / 32];

    int tid  = threadIdx.x;
    int lane = tid & 31, warp = tid >> 5;
    int path = blockIdx.x * MTPB + tid;
    bool active = (path < NMC);
    int pc = active ? path : (NMC - 1);
    int i0 = *i0p;

    // prologue: prefetch rows 0 and 1 into L1 (64 lines each)
    if (tid < ROWLN) {
        const char* p0 = (const char*)g_tab + tid * 128;
        const char* p1 = (const char*)(g_tab + NG) + tid * 128;
        asm volatile("prefetch.global.L1 [%0];" :: "l"(p0));
        asm volatile("prefetch.global.L1 [%0];" :: "l"(p1));
    }

    float y0 = fminf(fmaxf(y_seq[i0 - 1], 1e-4f), 1.0f - 1e-4f);
    float z  = logf(y0 / (1.0f - y0));
    const float* yobs = y_seq + i0;
    float ssum = 0.0f;
    float xik_next = __ldg(xi + pc);

    for (int t = 0; t < T_STEPS; t++) {
        // prefetch row t+2 into L1 (no dependency, no sync)
        if (t + 2 < T_STEPS && tid < ROWLN) {
            const char* p = (const char*)(g_tab + (size_t)(t + 2) * NG) + tid * 128;
            asm volatile("prefetch.global.L1 [%0];" :: "l"(p));
        }

        float xik = xik_next;
        int tn = (t + 1 < T_STEPS) ? (t + 1) : t;
        xik_next = __ldg(xi + (size_t)tn * NMC + pc);
        float yt = __ldg(yobs + t) - 0.5f;

        // grid position (stencil i-1..i+2 clamped in range)
        float u = fmaf(z, INVH, -ZMIN * INVH);
        u = fminf(fmaxf(u, 1.0f), (float)(NG - 3));
        int i = (int)u;
        if (i > NG - 3) i = NG - 3;
        float s = u - (float)i;

        const float2* row = g_tab + (size_t)t * NG;
        float2 pm = __ldg(row + i - 1);
        float2 p0 = __ldg(row + i);
        float2 p1 = __ldg(row + i + 1);
        float2 p2 = __ldg(row + i + 2);

        float sm1 = s - 1.0f, sm2 = s - 2.0f, sp1 = s + 1.0f;
        float wm = -s * sm1 * sm2 * (1.0f / 6.0f);
        float w0 =  sp1 * sm1 * sm2 * 0.5f;
        float w1 = -sp1 * s * sm2 * 0.5f;
        float w2 =  sp1 * s * sm1 * (1.0f / 6.0f);

        float F = wm * pm.x + w0 * p0.x + w1 * p1.x + w2 * p2.x;
        float G = wm * pm.y + w0 * p0.y + w1 * p1.y + w2 * p2.y;

        z = z + F + G * xik;

        float th;
        asm("tanh.approx.f32 %0, %1;\n" : "=f"(th) : "f"(0.5f * z));
        float dy = yt - 0.5f * th;
        ssum = fmaf(dy, dy, ssum);
    }

    if (!active) ssum = 0.0f;

#pragma unroll
    for (int o = 16; o; o >>= 1) ssum += __shfl_xor_sync(0xffffffffu, ssum, o);
    if (lane == 0) red[warp] = ssum;
    __syncthreads();
    if (warp == 0) {
        float s = (lane < MTPB / 32) ? red[lane] : 0.0f;
#pragma unroll
        for (int o = 4; o; o >>= 1) s += __shfl_xor_sync(0xffffffffu, s, o);
        if (lane == 0) g_part[blockIdx.x] = s;
    }
}

// ---------------------------------------------------------------------------
__global__ void fin_kernel(const float* __restrict__ lsop, float* __restrict__ out)
{
    int lane = threadIdx.x;
    float s = 0.0f;
    for (int i = lane; i < NCTA; i += 32) s += g_part[i];
#pragma unroll
    for (int o = 16; o; o >>= 1) s += __shfl_xor_sync(0xffffffffu, s, o);
    if (lane == 0) {
        float lso = *lsop;
        float sig = expf(lso) + 1e-8f;
        out[0] = 0.5f * s / ((float)T_STEPS * (float)NMC) / (sig * sig) + lso;
    }
}

// ---------------------------------------------------------------------------
extern "C" void kernel_launch(void* const* d_in, const int* in_sizes, int n_in,
                              void* d_out, int out_size)
{
    const float* X_seq = (const float*)d_in[0];
    const float* y_seq = (const float*)d_in[1];
    const float* kappa = (const float*)d_in[2];
    const float* a     = (const float*)d_in[3];
    const float* b0    = (const float*)d_in[4];
    const float* b1    = (const float*)d_in[5];
    const float* b2    = (const float*)d_in[6];
    const float* S     = (const float*)d_in[7];
    const float* lso   = (const float*)d_in[8];
    const float* dW1   = (const float*)d_in[9];
    const float* db1   = (const float*)d_in[10];
    const float* dW2   = (const float*)d_in[11];
    const float* db2   = (const float*)d_in[12];
    const float* dW3   = (const float*)d_in[13];
    const float* db3   = (const float*)d_in[14];
    const float* gW1   = (const float*)d_in[15];
    const float* gb1   = (const float*)d_in[16];
    const float* gW2   = (const float*)d_in[17];
    const float* gb2   = (const float*)d_in[18];
    const float* gW3   = (const float*)d_in[19];
    const float* gb3   = (const float*)d_in[20];
    const float* xi    = (const float*)d_in[21];
    const int*   i0    = (const int*)d_in[22];

    prep_kernel<<<T_STEPS, 128>>>(X_seq, a, b0, b1, b2, S, dW1, db1, gW1, gb1, i0);
    table_kernel<<<NCTA, TPB>>>(kappa, dW2, db2, dW3, db3, gW2, gb2, gW3, gb3);
    nop_kernel<<<1, 32>>>();   // padding: ncu -s 5 -> scan_kernel
    scan_kernel<<<NCTA, MTPB>>>(y_seq, xi, i0);
    fin_kernel<<<1, 32>>>(lso, (float*)d_out);
}